// round 16
// baseline (speedup 1.0000x reference)
#include <cuda_runtime.h>
#include <cuda_bf16.h>
#include <stdint.h>

#define TPB 512
#define MAX_PART 8192

__device__ float g_part[MAX_PART];
__device__ unsigned int g_ticket = 0;   // reset by last block every call

// 4 lanes per sample, H = 120. Single launch; last block finalizes.
__global__ void __launch_bounds__(TPB) runway_loss_h120(
        const float* __restrict__ pred,
        const unsigned char* __restrict__ mask,
        const float* __restrict__ runway,
        float* __restrict__ out,
        int B) {
    const unsigned FULL = 0xFFFFFFFFu;
    int t   = blockIdx.x * TPB + threadIdx.x;
    int g   = t >> 2;          // sample index
    int sub = t & 3;           // lane within 4-lane group
    bool active = (g < B);

    // ---- front-batched independent loads: mask quads + runway dir ----
    int ones = 0;
    float2 rdir = make_float2(0.0f, 0.0f);
    if (active) {
        const uint2* row = (const uint2*)(mask + (size_t)g * 120);
        int base = sub * 4;                     // uint2 idx: 0,4,8,12 (15/row)
        uint2 a = row[base];
        uint2 b = row[base + 1];
        uint2 c = row[base + 2];
        uint2 d = make_uint2(0u, 0u);
        if (base + 3 < 15) d = row[base + 3];   // lane 3 reads only 3
        rdir = *(const float2*)(runway + (size_t)g * 4 + 2);
        ones = __popc(a.x) + __popc(a.y) + __popc(b.x) + __popc(b.y)
             + __popc(c.x) + __popc(c.y) + __popc(d.x) + __popc(d.y);
    }
    // group reduce (4-lane groups xor-closed under offsets 1,2)
    ones += __shfl_xor_sync(FULL, ones, 1);
    ones += __shfl_xor_sync(FULL, ones, 2);

    float px = 0.0f, py = 0.0f;
    if (active) {
        int idx = 120 - ones - 4 + sub;         // L - 4 + sub
        if (idx < 0) idx = 0;
        if (idx > 119) idx = 119;
        const float* p = pred + (size_t)g * 360 + idx * 3;
        px = p[0];
        py = p[1];
    }

    // neighbor point (lane sub gets lane sub+1's point; valid for sub<3)
    float nx = __shfl_down_sync(FULL, px, 1);
    float ny = __shfl_down_sync(FULL, py, 1);

    float term = 0.0f;
    if (active && sub < 3) {
        float rx = rdir.x, ry = rdir.y;
        float dx = nx - px;
        float dy = ny - py;
        float d2 = dx * dx + dy * dy;
        float r2 = rx * rx + ry * ry;
        // cos = dot / (|d||r|); eps (1e-6) negligible vs |d|~1e3, |r|~1
        float cs = (dx * rx + dy * ry) * rsqrtf(d2 * r2);
        float u  = 1.0f - cs;
        term = u * u;
    }
    term += __shfl_xor_sync(FULL, term, 1);
    term += __shfl_xor_sync(FULL, term, 2);
    float per = (sub == 0 && active) ? term * (1.0f / 3.0f) : 0.0f;

    // ---- warp reduce (only sub==0 lanes nonzero) ----
    per += __shfl_xor_sync(FULL, per, 4);
    per += __shfl_xor_sync(FULL, per, 8);
    per += __shfl_xor_sync(FULL, per, 16);

    // ---- block reduce -> per-block partial, ticket finalize ----
    __shared__ float wsum[TPB / 32];
    __shared__ bool s_last;
    int lane = threadIdx.x & 31;
    int wid  = threadIdx.x >> 5;
    if (lane == 0) wsum[wid] = per;
    __syncthreads();
    if (threadIdx.x == 0) {
        float bsum = 0.0f;
        #pragma unroll
        for (int i = 0; i < TPB / 32; i++) bsum += wsum[i];
        g_part[blockIdx.x] = bsum;
        __threadfence();
        unsigned int tkt = atomicAdd(&g_ticket, 1u);
        s_last = (tkt == gridDim.x - 1);
    }
    __syncthreads();

    if (s_last) {
        __threadfence();                        // acquire all g_part writes
        __shared__ double dred[TPB];
        double dv = 0.0;
        for (int i = threadIdx.x; i < (int)gridDim.x; i += TPB)
            dv += (double)g_part[i];
        dred[threadIdx.x] = dv;
        __syncthreads();
        #pragma unroll
        for (int o = TPB / 2; o >= 1; o >>= 1) {
            if (threadIdx.x < o) dred[threadIdx.x] += dred[threadIdx.x + o];
            __syncthreads();
        }
        if (threadIdx.x == 0) {
            out[0] = (float)(dred[0] / (double)B);
            g_ticket = 0;
        }
    }
}

// ---------------- generic fallback (thread-per-sample, single launch) ----------------
__global__ void __launch_bounds__(256) runway_loss_generic(
        const float* __restrict__ pred,
        const unsigned char* __restrict__ mask,
        const float* __restrict__ runway,
        float* __restrict__ out,
        int B, int H) {
    int s = blockIdx.x * blockDim.x + threadIdx.x;
    float contrib = 0.0f;
    if (s < B) {
        const unsigned char* mrow = mask + (size_t)s * H;
        int ones = 0;
        for (int i = 0; i < H; i++) ones += (int)mrow[i];
        int L = H - ones;
        float rx = runway[(size_t)s * 4 + 2];
        float ry = runway[(size_t)s * 4 + 3];
        const float* prow = pred + (size_t)s * H * 3;
        float px[4], py[4];
        for (int j = 0; j < 4; j++) {
            int idx = L - 4 + j;
            if (idx < 0) idx = 0;
            if (idx > H - 1) idx = H - 1;
            px[j] = prow[idx * 3 + 0];
            py[j] = prow[idx * 3 + 1];
        }
        float r2 = rx * rx + ry * ry;
        float acc = 0.0f;
        for (int j = 0; j < 3; j++) {
            float dx = px[j + 1] - px[j];
            float dy = py[j + 1] - py[j];
            float d2 = dx * dx + dy * dy;
            float cs = (dx * rx + dy * ry) * rsqrtf(d2 * r2);
            float u  = 1.0f - cs;
            acc += u * u;
        }
        contrib = acc * (1.0f / 3.0f);
    }
    __shared__ float red[256];
    red[threadIdx.x] = contrib;
    __syncthreads();
    for (int o = 128; o >= 32; o >>= 1) {
        if (threadIdx.x < o) red[threadIdx.x] += red[threadIdx.x + o];
        __syncthreads();
    }
    __shared__ bool s_last;
    if (threadIdx.x < 32) {
        float v = red[threadIdx.x];
        for (int o = 16; o; o >>= 1)
            v += __shfl_xor_sync(0xFFFFFFFFu, v, o);
        if (threadIdx.x == 0) {
            g_part[blockIdx.x] = v;
            __threadfence();
            unsigned int tkt = atomicAdd(&g_ticket, 1u);
            s_last = (tkt == gridDim.x - 1);
        }
    }
    __syncthreads();
    if (s_last) {
        __threadfence();
        __shared__ double dred[256];
        double dv = 0.0;
        for (int i = threadIdx.x; i < (int)gridDim.x; i += 256)
            dv += (double)g_part[i];
        dred[threadIdx.x] = dv;
        __syncthreads();
        for (int o = 128; o >= 1; o >>= 1) {
            if (threadIdx.x < o) dred[threadIdx.x] += dred[threadIdx.x + o];
            __syncthreads();
        }
        if (threadIdx.x == 0) {
            out[0] = (float)(dred[0] / (double)B);
            g_ticket = 0;
        }
    }
}

extern "C" void kernel_launch(void* const* d_in, const int* in_sizes, int n_in,
                              void* d_out, int out_size) {
    const float*         pred   = (const float*)d_in[0];
    // d_in[1] = target_abs (unused by the reference)
    const unsigned char* mask   = (const unsigned char*)d_in[2];
    const float*         runway = (const float*)d_in[3];
    float*               out    = (float*)d_out;

    int B = in_sizes[3] / 4;          // runway is (B, 4)
    int H = in_sizes[2] / B;          // mask is (B, H)

    long long threads = (long long)B * 4;
    int blocks = (int)((threads + TPB - 1) / TPB);

    if (H == 120 && blocks <= MAX_PART) {
        runway_loss_h120<<<blocks, TPB>>>(pred, mask, runway, out, B);
    } else {
        int gblocks = (B + 255) / 256;
        if (gblocks > MAX_PART) gblocks = MAX_PART;
        runway_loss_generic<<<gblocks, 256>>>(pred, mask, runway, out, B, H);
    }
}

// round 17
// speedup vs baseline: 1.3579x; 1.3579x over previous
#include <cuda_runtime.h>
#include <cuda_bf16.h>
#include <stdint.h>

#define EPSF 1e-6f
#define TPB 256

__device__ double g_acc = 0.0;          // reset by last block every call
__device__ unsigned int g_ticket = 0;   // reset by last block every call

// 4 lanes cooperate per sample. H = 120 specialization. Single launch:
// last block to finish writes out[0] and resets the accumulators.
__global__ void __launch_bounds__(TPB) runway_loss_h120(
        const float* __restrict__ pred,
        const unsigned char* __restrict__ mask,
        const float* __restrict__ runway,
        float* __restrict__ out,
        int B) {
    const unsigned FULL = 0xFFFFFFFFu;
    int t   = blockIdx.x * TPB + threadIdx.x;
    int g   = t >> 2;          // sample index
    int sub = t & 3;           // lane within 4-lane group
    bool active = (g < B);

    float per = 0.0f;          // per-sample contribution (sub==0 lanes only)

    // ---- mask popcount: each lane reads up to 4 uint2 (8B-aligned, 120B rows) ----
    int ones = 0;
    float px = 0.0f, py = 0.0f;
    if (active) {
        const uint2* row = (const uint2*)(mask + (size_t)g * 120);
        int base = sub * 4;                     // uint2 index: 0,4,8,12 (15 total)
        uint2 a = row[base];
        uint2 b = row[base + 1];
        uint2 c = row[base + 2];
        uint2 d = make_uint2(0u, 0u);
        if (base + 3 < 15) d = row[base + 3];   // lane 3 reads only 3 words
        ones = __popc(a.x) + __popc(a.y) + __popc(b.x) + __popc(b.y)
             + __popc(c.x) + __popc(c.y) + __popc(d.x) + __popc(d.y);
    }
    // group reduce (4-lane groups are xor-closed under offsets 1,2)
    ones += __shfl_xor_sync(FULL, ones, 1);
    ones += __shfl_xor_sync(FULL, ones, 2);

    float2 rdir = make_float2(0.0f, 0.0f);
    if (active) {
        int L = 120 - ones;                     // valid length
        int idx = L - 4 + sub;
        if (idx < 0) idx = 0;
        if (idx > 119) idx = 119;
        const float* p = pred + (size_t)g * 360 + idx * 3;
        px = p[0];
        py = p[1];
        rdir = *(const float2*)(runway + (size_t)g * 4 + 2);
    }

    // neighbor point (lane sub gets lane sub+1's point; lane 3 result unused)
    float nx = __shfl_down_sync(FULL, px, 1);
    float ny = __shfl_down_sync(FULL, py, 1);

    float term = 0.0f;
    if (active && sub < 3) {
        float rx = rdir.x, ry = rdir.y;
        float rn = __fsqrt_rn(rx * rx + ry * ry) + EPSF;
        rx = __fdiv_rn(rx, rn);
        ry = __fdiv_rn(ry, rn);

        float dx = nx - px;
        float dy = ny - py;
        float dn = __fsqrt_rn(dx * dx + dy * dy) + EPSF;
        float cs = __fdiv_rn(dx, dn) * rx + __fdiv_rn(dy, dn) * ry;
        float u  = 1.0f - cs;
        term = u * u;
    }
    term += __shfl_xor_sync(FULL, term, 1);
    term += __shfl_xor_sync(FULL, term, 2);
    if (active && sub == 0)
        per = __fdiv_rn(term, 3.0f);            // mean over 3 directions

    // ---- warp reduce (sub!=0 lanes hold 0) ----
    per += __shfl_xor_sync(FULL, per, 4);
    per += __shfl_xor_sync(FULL, per, 8);
    per += __shfl_xor_sync(FULL, per, 16);

    // ---- block reduce: one double atomic per block, then last-block finalize ----
    __shared__ float wsum[TPB / 32];
    int lane = threadIdx.x & 31;
    int wid  = threadIdx.x >> 5;
    if (lane == 0) wsum[wid] = per;
    __syncthreads();
    if (threadIdx.x == 0) {
        float bsum = 0.0f;
        #pragma unroll
        for (int i = 0; i < TPB / 32; i++) bsum += wsum[i];
        atomicAdd(&g_acc, (double)bsum);
        __threadfence();
        unsigned int tkt = atomicAdd(&g_ticket, 1u);
        if (tkt == gridDim.x - 1) {
            // all blocks' g_acc additions are visible (they precede their
            // ticket increments, each ordered by __threadfence)
            out[0] = (float)(g_acc / (double)B);
            g_acc = 0.0;
            g_ticket = 0;
        }
    }
}

// Generic fallback (thread-per-sample) for unexpected H. Same single-launch pattern.
__global__ void __launch_bounds__(TPB) runway_loss_generic(
        const float* __restrict__ pred,
        const unsigned char* __restrict__ mask,
        const float* __restrict__ runway,
        float* __restrict__ out,
        int B, int H) {
    int s = blockIdx.x * blockDim.x + threadIdx.x;
    float contrib = 0.0f;
    if (s < B) {
        const unsigned char* mrow = mask + (size_t)s * H;
        int ones = 0;
        for (int i = 0; i < H; i++) ones += (int)mrow[i];
        int L = H - ones;
        float rx = runway[(size_t)s * 4 + 2];
        float ry = runway[(size_t)s * 4 + 3];
        float rn = __fsqrt_rn(rx * rx + ry * ry) + EPSF;
        rx = __fdiv_rn(rx, rn);
        ry = __fdiv_rn(ry, rn);
        const float* prow = pred + (size_t)s * H * 3;
        float px[4], py[4];
        for (int j = 0; j < 4; j++) {
            int idx = L - 4 + j;
            if (idx < 0) idx = 0;
            if (idx > H - 1) idx = H - 1;
            px[j] = prow[idx * 3 + 0];
            py[j] = prow[idx * 3 + 1];
        }
        float acc = 0.0f;
        for (int j = 0; j < 3; j++) {
            float dx = px[j + 1] - px[j];
            float dy = py[j + 1] - py[j];
            float dn = __fsqrt_rn(dx * dx + dy * dy) + EPSF;
            float cs = __fdiv_rn(dx, dn) * rx + __fdiv_rn(dy, dn) * ry;
            float u  = 1.0f - cs;
            acc += u * u;
        }
        contrib = __fdiv_rn(acc, 3.0f);
    }
    __shared__ float red[TPB];
    red[threadIdx.x] = contrib;
    __syncthreads();
    for (int o = TPB / 2; o >= 32; o >>= 1) {
        if (threadIdx.x < o) red[threadIdx.x] += red[threadIdx.x + o];
        __syncthreads();
    }
    if (threadIdx.x < 32) {
        float v = red[threadIdx.x];
        for (int o = 16; o; o >>= 1)
            v += __shfl_xor_sync(0xFFFFFFFFu, v, o);
        if (threadIdx.x == 0) {
            atomicAdd(&g_acc, (double)v);
            __threadfence();
            unsigned int tkt = atomicAdd(&g_ticket, 1u);
            if (tkt == gridDim.x - 1) {
                out[0] = (float)(g_acc / (double)B);
                g_acc = 0.0;
                g_ticket = 0;
            }
        }
    }
}

extern "C" void kernel_launch(void* const* d_in, const int* in_sizes, int n_in,
                              void* d_out, int out_size) {
    const float*         pred   = (const float*)d_in[0];
    // d_in[1] = target_abs (unused by the reference)
    const unsigned char* mask   = (const unsigned char*)d_in[2];
    const float*         runway = (const float*)d_in[3];
    float*               out    = (float*)d_out;

    int B = in_sizes[3] / 4;          // runway is (B, 4)
    int H = in_sizes[2] / B;          // mask is (B, H)

    if (H == 120) {
        int threads_needed = B * 4;
        int blocks = (threads_needed + TPB - 1) / TPB;
        runway_loss_h120<<<blocks, TPB>>>(pred, mask, runway, out, B);
    } else {
        int blocks = (B + TPB - 1) / TPB;
        runway_loss_generic<<<blocks, TPB>>>(pred, mask, runway, out, B, H);
    }
}